// round 1
// baseline (speedup 1.0000x reference)
#include <cuda_runtime.h>

// ---------------- sizes ----------------
// x: 16x256x256x3 ; enc1 out: 16x128x128x64 ; enc2/f/q: 16x64x64x128
// y: 16x256x256x3 ; out = concat(y, f, q)
#define Y_SZ  (16*256*256*3)
#define F_SZ  (16*64*64*128)

// weight scratch offsets (floats), all 16B-aligned
#define WT_ENC2   0
#define WT_ENC3   131072
#define WT_ERB1A  278528
#define WT_ERB1B  315392
#define WT_ERB2A  319488
#define WT_ERB2B  356352
#define WT_DEC    360448
#define WT_DRB1A  507904
#define WT_DRB1B  544768
#define WT_DRB2A  548864
#define WT_DRB2B  585728
#define WT_DT1    589824
#define WT_DT2    720896

__device__ __align__(16) float g_A[16*128*128*64];   // enc1 out / dt1 out
__device__ __align__(16) float g_B1[16*64*64*128];
__device__ __align__(16) float g_B2[16*64*64*128];
__device__ __align__(16) float g_T[16*64*64*32];
__device__ __align__(16) float g_norme[512];
__device__ __align__(16) float g_wts[1 << 20];

__device__ __forceinline__ float dot4(float4 a, float4 b) {
    return fmaf(a.x, b.x, fmaf(a.y, b.y, fmaf(a.z, b.z, a.w * b.w)));
}
__device__ __forceinline__ float4 relu4(float4 a) {
    a.x = fmaxf(a.x, 0.f); a.y = fmaxf(a.y, 0.f);
    a.z = fmaxf(a.z, 0.f); a.w = fmaxf(a.w, 0.f);
    return a;
}

// [k][ic][oc] -> [k][oc][ic]
__global__ void transpose_w(const float* __restrict__ in, float* __restrict__ out,
                            int K, int IC, int OC) {
    int i = blockIdx.x * blockDim.x + threadIdx.x;
    int total = K * IC * OC;
    if (i >= total) return;
    int oc = i % OC;
    int ic = (i / OC) % IC;
    int k  = i / (OC * IC);
    out[(k * OC + oc) * IC + ic] = in[i];
}

__global__ void norme_kernel(const float* __restrict__ emb, float* __restrict__ norme) {
    int k = blockIdx.x * blockDim.x + threadIdx.x;
    if (k >= 512) return;
    const float4* e = (const float4*)(emb + k * 128);
    float s = 0.f;
#pragma unroll 8
    for (int i = 0; i < 32; i++) {
        float4 v = e[i];
        s = fmaf(v.x, v.x, s); s = fmaf(v.y, v.y, s);
        s = fmaf(v.z, v.z, s); s = fmaf(v.w, v.w, s);
    }
    norme[k] = s;
}

// ---------------- enc1: 4x4 s2, 3->64, pad 1, relu ----------------
__global__ void enc1_kernel(const float* __restrict__ x, const float* __restrict__ w,
                            const float* __restrict__ b, float* __restrict__ out) {
    int t = blockIdx.x * 256 + threadIdx.x;
    int oc = t & 63;
    int r = t >> 6;
    int ow = r & 127;
    int oh = (r >> 7) & 127;
    int n  = r >> 14;
    float acc = b[oc];
#pragma unroll
    for (int kh = 0; kh < 4; kh++) {
        int ih = 2 * oh - 1 + kh;
        if ((unsigned)ih >= 256u) continue;
#pragma unroll
        for (int kw = 0; kw < 4; kw++) {
            int iw = 2 * ow - 1 + kw;
            if ((unsigned)iw >= 256u) continue;
            const float* xp = x + ((n * 256 + ih) * 256 + iw) * 3;
            const float* wp = w + (kh * 4 + kw) * 3 * 64 + oc;
            acc = fmaf(xp[0], wp[0],   acc);
            acc = fmaf(xp[1], wp[64],  acc);
            acc = fmaf(xp[2], wp[128], acc);
        }
    }
    out[t] = fmaxf(acc, 0.f);
}

// ---------------- enc2: 4x4 s2, 64->128, pad 1, relu, wt [k][oc][ic] ----------------
__global__ void enc2_kernel(const float* __restrict__ in, const float* __restrict__ wt,
                            const float* __restrict__ b, float* __restrict__ out) {
    int t = blockIdx.x * 256 + threadIdx.x;
    int oc  = t & 127;
    int r   = t >> 7;
    int owq = r & 15;
    int oh  = (r >> 4) & 63;
    int n   = r >> 10;
    int ow0 = owq * 4;
    float bv = b[oc];
    float acc0 = bv, acc1 = bv, acc2 = bv, acc3 = bv;
#pragma unroll
    for (int kh = 0; kh < 4; kh++) {
        int ih = 2 * oh - 1 + kh;
        if ((unsigned)ih >= 128u) continue;
        const float* inrow = in + ((n * 128 + ih) * 128) * 64;
#pragma unroll
        for (int kw = 0; kw < 4; kw++) {
            const float4* wp = (const float4*)(wt + ((kh * 4 + kw) * 128 + oc) * 64);
            int iwb = 2 * ow0 - 1 + kw;
            int iw0 = iwb, iw1 = iwb + 2, iw2 = iwb + 4, iw3 = iwb + 6;
            bool v0 = (unsigned)iw0 < 128u, v1 = (unsigned)iw1 < 128u;
            bool v2 = (unsigned)iw2 < 128u, v3 = (unsigned)iw3 < 128u;
            const float4* p0 = (const float4*)(inrow + iw0 * 64);
            const float4* p1 = (const float4*)(inrow + iw1 * 64);
            const float4* p2 = (const float4*)(inrow + iw2 * 64);
            const float4* p3 = (const float4*)(inrow + iw3 * 64);
#pragma unroll 4
            for (int ic4 = 0; ic4 < 16; ic4++) {
                float4 w4 = wp[ic4];
                if (v0) acc0 += dot4(p0[ic4], w4);
                if (v1) acc1 += dot4(p1[ic4], w4);
                if (v2) acc2 += dot4(p2[ic4], w4);
                if (v3) acc3 += dot4(p3[ic4], w4);
            }
        }
    }
    float* op = out + ((n * 64 + oh) * 64 + ow0) * 128 + oc;
    op[0]   = fmaxf(acc0, 0.f);
    op[128] = fmaxf(acc1, 0.f);
    op[256] = fmaxf(acc2, 0.f);
    op[384] = fmaxf(acc3, 0.f);
}

// ---------------- generic 3x3 s1 conv on 16x64x64 grid, wt [k][oc][ic] ----------------
template<int IC, int OC, bool RELU_IN, bool HAS_BIAS>
__global__ void conv3x3_k(const float* __restrict__ in, const float* __restrict__ wt,
                          const float* __restrict__ bias, float* __restrict__ out) {
    int t = blockIdx.x * 256 + threadIdx.x;
    int oc  = t & (OC - 1);
    int r   = t / OC;
    int owq = r & 15;
    int oh  = (r >> 4) & 63;
    int n   = r >> 10;
    int ow0 = owq * 4;
    float acc0 = 0.f, acc1 = 0.f, acc2 = 0.f, acc3 = 0.f;
    if (HAS_BIAS) { float bv = bias[oc]; acc0 = acc1 = acc2 = acc3 = bv; }
#pragma unroll
    for (int kh = 0; kh < 3; kh++) {
        int ih = oh - 1 + kh;
        if ((unsigned)ih >= 64u) continue;
        const float* inrow = in + ((n * 64 + ih) * 64) * IC;
#pragma unroll
        for (int kw = 0; kw < 3; kw++) {
            int iw0 = ow0 - 1 + kw;
            const float4* wp = (const float4*)(wt + ((kh * 3 + kw) * OC + oc) * IC);
            bool v0 = (unsigned)(iw0)     < 64u;
            bool v1 = (unsigned)(iw0 + 1) < 64u;
            bool v2 = (unsigned)(iw0 + 2) < 64u;
            bool v3 = (unsigned)(iw0 + 3) < 64u;
            const float4* p0 = (const float4*)(inrow + (iw0)     * IC);
            const float4* p1 = (const float4*)(inrow + (iw0 + 1) * IC);
            const float4* p2 = (const float4*)(inrow + (iw0 + 2) * IC);
            const float4* p3 = (const float4*)(inrow + (iw0 + 3) * IC);
#pragma unroll 4
            for (int ic4 = 0; ic4 < IC / 4; ic4++) {
                float4 w4 = wp[ic4];
                if (v0) { float4 x4 = p0[ic4]; if (RELU_IN) x4 = relu4(x4); acc0 += dot4(x4, w4); }
                if (v1) { float4 x4 = p1[ic4]; if (RELU_IN) x4 = relu4(x4); acc1 += dot4(x4, w4); }
                if (v2) { float4 x4 = p2[ic4]; if (RELU_IN) x4 = relu4(x4); acc2 += dot4(x4, w4); }
                if (v3) { float4 x4 = p3[ic4]; if (RELU_IN) x4 = relu4(x4); acc3 += dot4(x4, w4); }
            }
        }
    }
    float* op = out + ((n * 64 + oh) * 64 + ow0) * OC + oc;
    op[0]      = acc0;
    op[OC]     = acc1;
    op[2 * OC] = acc2;
    op[3 * OC] = acc3;
}

// ---------------- 1x1 conv (relu on input) + residual add, 32->128 ----------------
template<bool RELU_OUT>
__global__ void conv1x1_res(const float* __restrict__ tin, const float* __restrict__ res,
                            const float* __restrict__ wt, float* __restrict__ out) {
    int t = blockIdx.x * 256 + threadIdx.x;
    int oc = t & 127;
    int pq = t >> 7;
    long p0 = (long)pq * 4;
    const float4* wp = (const float4*)(wt + oc * 32);
    const float4* t0 = (const float4*)(tin + (p0)     * 32);
    const float4* t1 = (const float4*)(tin + (p0 + 1) * 32);
    const float4* t2 = (const float4*)(tin + (p0 + 2) * 32);
    const float4* t3 = (const float4*)(tin + (p0 + 3) * 32);
    float acc0 = 0.f, acc1 = 0.f, acc2 = 0.f, acc3 = 0.f;
#pragma unroll
    for (int ic4 = 0; ic4 < 8; ic4++) {
        float4 w4 = wp[ic4];
        acc0 += dot4(relu4(t0[ic4]), w4);
        acc1 += dot4(relu4(t1[ic4]), w4);
        acc2 += dot4(relu4(t2[ic4]), w4);
        acc3 += dot4(relu4(t3[ic4]), w4);
    }
    long o = p0 * 128 + oc;
    float v0 = res[o]       + acc0;
    float v1 = res[o + 128] + acc1;
    float v2 = res[o + 256] + acc2;
    float v3 = res[o + 384] + acc3;
    if (RELU_OUT) {
        v0 = fmaxf(v0, 0.f); v1 = fmaxf(v1, 0.f);
        v2 = fmaxf(v2, 0.f); v3 = fmaxf(v3, 0.f);
    }
    out[o] = v0; out[o + 128] = v1; out[o + 256] = v2; out[o + 384] = v3;
}

// ---------------- VQ: argmin over 512 codes + gather ----------------
__global__ void __launch_bounds__(128) vq_kernel(const float* __restrict__ f,
                                                 const float* __restrict__ emb,
                                                 const float* __restrict__ norme,
                                                 float* __restrict__ q) {
    __shared__ float xs[8 * 128];
    __shared__ float rdist[8 * 128];
    __shared__ int   ridx[8 * 128];
    __shared__ int   best[8];
    int tid = threadIdx.x;  // 0..127
    long pixel0 = (long)blockIdx.x * 8;
    const float4* fin = (const float4*)(f + pixel0 * 128);
    float4* xs4 = (float4*)xs;
    xs4[tid]       = fin[tid];
    xs4[tid + 128] = fin[tid + 128];
    __syncthreads();

    float acc[4][8];
#pragma unroll
    for (int j = 0; j < 4; j++)
#pragma unroll
        for (int p = 0; p < 8; p++) acc[j][p] = 0.f;

    const float4* ef4 = (const float4*)emb;
#pragma unroll 2
    for (int d4 = 0; d4 < 32; d4++) {
        float4 xv[8];
#pragma unroll
        for (int p = 0; p < 8; p++) xv[p] = xs4[p * 32 + d4];
#pragma unroll
        for (int j = 0; j < 4; j++) {
            int c = tid + 128 * j;
            float4 ev = ef4[c * 32 + d4];
#pragma unroll
            for (int p = 0; p < 8; p++) {
                acc[j][p] = fmaf(xv[p].x, ev.x, acc[j][p]);
                acc[j][p] = fmaf(xv[p].y, ev.y, acc[j][p]);
                acc[j][p] = fmaf(xv[p].z, ev.z, acc[j][p]);
                acc[j][p] = fmaf(xv[p].w, ev.w, acc[j][p]);
            }
        }
    }
#pragma unroll
    for (int p = 0; p < 8; p++) {
        float bd = 1e30f; int bi = 0;
#pragma unroll
        for (int j = 0; j < 4; j++) {
            int c = tid + 128 * j;
            float d = norme[c] - 2.f * acc[j][p];
            if (d < bd) { bd = d; bi = c; }   // j increasing => c increasing, strict < keeps first
        }
        rdist[p * 128 + tid] = bd;
        ridx[p * 128 + tid]  = bi;
    }
    __syncthreads();
    if (tid < 8) {
        int p = tid;
        float bd = 1e30f; int bi = 0x7fffffff;
        for (int u = 0; u < 128; u++) {
            float d = rdist[p * 128 + u];
            int   i = ridx[p * 128 + u];
            if (d < bd || (d == bd && i < bi)) { bd = d; bi = i; }
        }
        best[p] = bi;
    }
    __syncthreads();
#pragma unroll
    for (int p = 0; p < 8; p++)
        q[(pixel0 + p) * 128 + tid] = emb[best[p] * 128 + tid];
}

// ---------------- dt1: conv_transpose 4x4 s2, 128->64, relu; wt [k][oc][ic] ----------------
__global__ void dt1_kernel(const float* __restrict__ in, const float* __restrict__ wt,
                           const float* __restrict__ b, float* __restrict__ out) {
    int t = blockIdx.x * 256 + threadIdx.x;
    int oc = t & 63;
    int r  = t >> 6;
    int ow = r & 127;
    int oh = (r >> 7) & 127;
    int n  = r >> 14;
    float acc = b[oc];
#pragma unroll
    for (int dh = 0; dh < 2; dh++) {
        int kh = (oh & 1) + 2 * dh;
        int ih2 = oh + kh - 2;
        if (ih2 < 0 || ih2 >= 128) continue;
        int ih = ih2 >> 1;
#pragma unroll
        for (int dw = 0; dw < 2; dw++) {
            int kw = (ow & 1) + 2 * dw;
            int iw2 = ow + kw - 2;
            if (iw2 < 0 || iw2 >= 128) continue;
            int iw = iw2 >> 1;
            const float4* xp = (const float4*)(in + ((n * 64 + ih) * 64 + iw) * 128);
            const float4* wp = (const float4*)(wt + ((kh * 4 + kw) * 64 + oc) * 128);
#pragma unroll 8
            for (int ic4 = 0; ic4 < 32; ic4++)
                acc += dot4(xp[ic4], wp[ic4]);
        }
    }
    out[t] = fmaxf(acc, 0.f);
}

// ---------------- dt2: conv_transpose 4x4 s2, 64->3; wt [k][oc][ic] ----------------
__global__ void dt2_kernel(const float* __restrict__ in, const float* __restrict__ wt,
                           const float* __restrict__ b, float* __restrict__ out) {
    int t = blockIdx.x * 256 + threadIdx.x;
    int ow = t & 255;
    int oh = (t >> 8) & 255;
    int n  = t >> 16;
    float a0 = b[0], a1 = b[1], a2 = b[2];
#pragma unroll
    for (int dh = 0; dh < 2; dh++) {
        int kh = (oh & 1) + 2 * dh;
        int ih2 = oh + kh - 2;
        if (ih2 < 0 || ih2 >= 256) continue;
        int ih = ih2 >> 1;
#pragma unroll
        for (int dw = 0; dw < 2; dw++) {
            int kw = (ow & 1) + 2 * dw;
            int iw2 = ow + kw - 2;
            if (iw2 < 0 || iw2 >= 256) continue;
            int iw = iw2 >> 1;
            const float4* xp = (const float4*)(in + ((n * 128 + ih) * 128 + iw) * 64);
            const float* wb = wt + (kh * 4 + kw) * 3 * 64;
            const float4* w0 = (const float4*)(wb);
            const float4* w1 = (const float4*)(wb + 64);
            const float4* w2 = (const float4*)(wb + 128);
#pragma unroll 4
            for (int ic4 = 0; ic4 < 16; ic4++) {
                float4 x4 = xp[ic4];
                a0 += dot4(x4, w0[ic4]);
                a1 += dot4(x4, w1[ic4]);
                a2 += dot4(x4, w2[ic4]);
            }
        }
    }
    float* op = out + (long)((n * 256 + oh) * 256 + ow) * 3;
    op[0] = a0; op[1] = a1; op[2] = a2;
}

extern "C" void kernel_launch(void* const* d_in, const int* in_sizes, int n_in,
                              void* d_out, int out_size) {
    const float* x       = (const float*)d_in[0];
    const float* emb     = (const float*)d_in[1];
    const float* enc_w1  = (const float*)d_in[2];
    const float* enc_b1  = (const float*)d_in[3];
    const float* enc_w2  = (const float*)d_in[4];
    const float* enc_b2  = (const float*)d_in[5];
    const float* enc_w3  = (const float*)d_in[6];
    const float* enc_b3  = (const float*)d_in[7];
    const float* erb1_w1 = (const float*)d_in[8];
    const float* erb1_w2 = (const float*)d_in[9];
    const float* erb2_w1 = (const float*)d_in[10];
    const float* erb2_w2 = (const float*)d_in[11];
    const float* dec_w   = (const float*)d_in[12];
    const float* dec_b   = (const float*)d_in[13];
    const float* drb1_w1 = (const float*)d_in[14];
    const float* drb1_w2 = (const float*)d_in[15];
    const float* drb2_w1 = (const float*)d_in[16];
    const float* drb2_w2 = (const float*)d_in[17];
    const float* dt1_w   = (const float*)d_in[18];
    const float* dt1_b   = (const float*)d_in[19];
    const float* dt2_w   = (const float*)d_in[20];
    const float* dt2_b   = (const float*)d_in[21];

    float *pA, *pB1, *pB2, *pT, *pN, *pW;
    cudaGetSymbolAddress((void**)&pA,  g_A);
    cudaGetSymbolAddress((void**)&pB1, g_B1);
    cudaGetSymbolAddress((void**)&pB2, g_B2);
    cudaGetSymbolAddress((void**)&pT,  g_T);
    cudaGetSymbolAddress((void**)&pN,  g_norme);
    cudaGetSymbolAddress((void**)&pW,  g_wts);

    float* yout = (float*)d_out;
    float* fout = yout + Y_SZ;
    float* qout = fout + F_SZ;

    auto TR = [](const float* s, float* d, int K, int IC, int OC) {
        int total = K * IC * OC;
        transpose_w<<<(total + 255) / 256, 256>>>(s, d, K, IC, OC);
    };
    TR(enc_w2,  pW + WT_ENC2,  16, 64, 128);
    TR(enc_w3,  pW + WT_ENC3,  9, 128, 128);
    TR(erb1_w1, pW + WT_ERB1A, 9, 128, 32);
    TR(erb1_w2, pW + WT_ERB1B, 1, 32, 128);
    TR(erb2_w1, pW + WT_ERB2A, 9, 128, 32);
    TR(erb2_w2, pW + WT_ERB2B, 1, 32, 128);
    TR(dec_w,   pW + WT_DEC,   9, 128, 128);
    TR(drb1_w1, pW + WT_DRB1A, 9, 128, 32);
    TR(drb1_w2, pW + WT_DRB1B, 1, 32, 128);
    TR(drb2_w1, pW + WT_DRB2A, 9, 128, 32);
    TR(drb2_w2, pW + WT_DRB2B, 1, 32, 128);
    TR(dt1_w,   pW + WT_DT1,   16, 128, 64);
    TR(dt2_w,   pW + WT_DT2,   16, 64, 3);
    norme_kernel<<<2, 256>>>(emb, pN);

    // Encoder
    enc1_kernel<<<65536, 256>>>(x, enc_w1, enc_b1, pA);
    enc2_kernel<<<8192, 256>>>(pA, pW + WT_ENC2, enc_b2, pB1);
    conv3x3_k<128, 128, false, true><<<8192, 256>>>(pB1, pW + WT_ENC3, enc_b3, pB2);
    conv3x3_k<128, 32, true, false><<<2048, 256>>>(pB2, pW + WT_ERB1A, nullptr, pT);
    conv1x1_res<false><<<8192, 256>>>(pT, pB2, pW + WT_ERB1B, pB1);
    conv3x3_k<128, 32, true, false><<<2048, 256>>>(pB1, pW + WT_ERB2A, nullptr, pT);
    conv1x1_res<true><<<8192, 256>>>(pT, pB1, pW + WT_ERB2B, fout);  // f written to d_out

    // VQ
    vq_kernel<<<8192, 128>>>(fout, emb, pN, qout);                   // q written to d_out

    // Decoder
    conv3x3_k<128, 128, false, true><<<8192, 256>>>(qout, pW + WT_DEC, dec_b, pB1);
    conv3x3_k<128, 32, true, false><<<2048, 256>>>(pB1, pW + WT_DRB1A, nullptr, pT);
    conv1x1_res<false><<<8192, 256>>>(pT, pB1, pW + WT_DRB1B, pB2);
    conv3x3_k<128, 32, true, false><<<2048, 256>>>(pB2, pW + WT_DRB2A, nullptr, pT);
    conv1x1_res<true><<<8192, 256>>>(pT, pB2, pW + WT_DRB2B, pB1);
    dt1_kernel<<<65536, 256>>>(pB1, pW + WT_DT1, dt1_b, pA);
    dt2_kernel<<<4096, 256>>>(pA, pW + WT_DT2, dt2_b, yout);
}

// round 2
// speedup vs baseline: 6.7036x; 6.7036x over previous
#include <cuda_runtime.h>

#define Y_SZ  (16*256*256*3)
#define F_SZ  (16*64*64*128)

__device__ __align__(16) float g_A[16*128*128*64];   // enc1 out / dt1 out
__device__ __align__(16) float g_B1[16*64*64*128];
__device__ __align__(16) float g_B2[16*64*64*128];
__device__ __align__(16) float g_T[16*64*64*32];
__device__ __align__(16) float g_norme[512];
__device__ __align__(16) float g_embT[512*128];
__device__ __align__(16) float g_wdt2[16*3*64];

__device__ __forceinline__ float4 relu4(float4 a) {
    a.x = fmaxf(a.x, 0.f); a.y = fmaxf(a.y, 0.f);
    a.z = fmaxf(a.z, 0.f); a.w = fmaxf(a.w, 0.f);
    return a;
}
__device__ __forceinline__ float dot4(float4 a, float4 b) {
    return fmaf(a.x, b.x, fmaf(a.y, b.y, fmaf(a.z, b.z, a.w * b.w)));
}

// [k][ic][oc] -> [k][oc][ic]  (only used for dt2's tiny weights)
__global__ void transpose_w(const float* __restrict__ in, float* __restrict__ out,
                            int K, int IC, int OC) {
    int i = blockIdx.x * blockDim.x + threadIdx.x;
    int total = K * IC * OC;
    if (i >= total) return;
    int oc = i % OC;
    int ic = (i / OC) % IC;
    int k  = i / (OC * IC);
    out[(k * OC + oc) * IC + ic] = in[i];
}

__global__ void norme_kernel(const float* __restrict__ emb, float* __restrict__ norme) {
    int k = blockIdx.x * blockDim.x + threadIdx.x;
    if (k >= 512) return;
    const float4* e = (const float4*)(emb + k * 128);
    float s = 0.f;
#pragma unroll 8
    for (int i = 0; i < 32; i++) {
        float4 v = e[i];
        s = fmaf(v.x, v.x, s); s = fmaf(v.y, v.y, s);
        s = fmaf(v.z, v.z, s); s = fmaf(v.w, v.w, s);
    }
    norme[k] = s;
}

// emb [c][d] -> embT float4 layout [d4][c]
__global__ void embT_kernel(const float* __restrict__ emb, float* __restrict__ embT) {
    int i = blockIdx.x * 256 + threadIdx.x;
    if (i >= 512 * 32) return;
    int c = i & 511, d4 = i >> 9;
    float4 v = *(const float4*)(emb + c * 128 + 4 * d4);
    *(float4*)(embT + (d4 * 512 + c) * 4) = v;
}

// ================= tiled implicit-GEMM conv =================
// MODE 0: standard conv (KHxKW, stride, pad) on square IH grid, out 64x64.
// MODE 1: dt1 deconv per parity class (blockIdx.y = 2*po+pw), 2x2 taps on 64 grid,
//         output scattered to the 128x128 grid.
// Weights in ORIGINAL layout [tap][ic][oc] (oc contiguous).
template<int MODE, int KH, int KW, int STRIDE, int PAD, int IH,
         int IC, int OC, int BM, int TM, int TN,
         bool RELU_IN, bool HAS_BIAS, bool RELU_OUT>
__global__ void __launch_bounds__(256, 2) conv_gemm(
    const float* __restrict__ in, const float* __restrict__ w,
    const float* __restrict__ bias, float* __restrict__ out)
{
    constexpr int BK = 32;
    constexpr int BN = OC;
    constexpr int TX = BN / TN;
    constexpr int ASTR = BM + 1;
    constexpr int NTAPS = (MODE == 0) ? KH * KW : 4;
    constexpr int SE = (MODE == 0) ? STRIDE : 1;

    __shared__ float As[BK * ASTR];
    __shared__ float Bs[BK * BN];

    int tid = threadIdx.x;
    int m0 = blockIdx.x * BM;
    int po = 0, pw = 0;
    if (MODE == 1) { po = blockIdx.y >> 1; pw = blockIdx.y & 1; }

    int tx = tid % TX, ty = tid / TX;
    int c4 = tid & 7;         // channel-quad within BK
    int mp = tid >> 3;        // pixel within 32-pixel pass

    float acc[TM][TN];
#pragma unroll
    for (int i = 0; i < TM; i++)
#pragma unroll
        for (int j = 0; j < TN; j++) acc[i][j] = 0.f;

    for (int tap = 0; tap < NTAPS; tap++) {
        int hoff, woff, wtap;
        if (MODE == 0) {
            int kh = tap / KW, kw = tap % KW;
            hoff = kh - PAD; woff = kw - PAD; wtap = tap;
        } else {
            int dh = tap >> 1, dw = tap & 1;
            hoff = po + dh - 1; woff = pw + dw - 1;
            wtap = (po + 2 * dh) * 4 + (pw + 2 * dw);
        }
        for (int kc = 0; kc < IC / BK; kc++) {
            __syncthreads();
            // ---- load A tile (BM pixels x BK channels), transposed into As[k][m]
#pragma unroll
            for (int pass = 0; pass < BM / 32; pass++) {
                int m = mp + pass * 32;
                int p = m0 + m;
                int n_img = p >> 12;
                int oh = (p >> 6) & 63;
                int ow = p & 63;
                int ih = oh * SE + hoff;
                int iw = ow * SE + woff;
                float4 v = make_float4(0.f, 0.f, 0.f, 0.f);
                if ((unsigned)ih < (unsigned)IH && (unsigned)iw < (unsigned)IH) {
                    v = *(const float4*)(in + ((n_img * IH + ih) * IH + iw) * IC
                                            + kc * BK + 4 * c4);
                    if (RELU_IN) v = relu4(v);
                }
                int kk = 4 * c4;
                As[(kk + 0) * ASTR + m] = v.x;
                As[(kk + 1) * ASTR + m] = v.y;
                As[(kk + 2) * ASTR + m] = v.z;
                As[(kk + 3) * ASTR + m] = v.w;
            }
            // ---- load B tile (BK x BN), oc contiguous -> coalesced
            {
                const float* wb = w + (wtap * IC + kc * BK) * OC;
#pragma unroll
                for (int i = 0; i < (BK * BN / 4) / 256; i++) {
                    int idx = tid + i * 256;
                    int kr = idx / (BN / 4);
                    int n4 = idx % (BN / 4);
                    *(float4*)(Bs + kr * BN + 4 * n4) =
                        *(const float4*)(wb + kr * OC + 4 * n4);
                }
            }
            __syncthreads();
            // ---- inner product
#pragma unroll 8
            for (int k = 0; k < BK; k++) {
                float a[TM], b[TN];
#pragma unroll
                for (int i = 0; i < TM; i++) a[i] = As[k * ASTR + ty * TM + i];
#pragma unroll
                for (int j = 0; j < TN / 4; j++)
                    *(float4*)(b + 4 * j) = *(const float4*)(Bs + k * BN + tx * TN + 4 * j);
#pragma unroll
                for (int i = 0; i < TM; i++)
#pragma unroll
                    for (int j = 0; j < TN; j++)
                        acc[i][j] = fmaf(a[i], b[j], acc[i][j]);
            }
        }
    }
    // ---- epilogue
    float bv[TN];
#pragma unroll
    for (int j = 0; j < TN; j++) bv[j] = HAS_BIAS ? bias[tx * TN + j] : 0.f;
    int base_m = m0 + ty * TM;
#pragma unroll
    for (int i = 0; i < TM; i++) {
        int p = base_m + i;
        float v[TN];
#pragma unroll
        for (int j = 0; j < TN; j++) {
            float t = acc[i][j] + bv[j];
            v[j] = RELU_OUT ? fmaxf(t, 0.f) : t;
        }
        long oaddr;
        if (MODE == 0) {
            oaddr = (long)p * OC + tx * TN;
        } else {
            int n_img = p >> 12, a2 = (p >> 6) & 63, b2 = p & 63;
            oaddr = (((long)n_img * 128 + 2 * a2 + po) * 128 + 2 * b2 + pw) * OC + tx * TN;
        }
#pragma unroll
        for (int j = 0; j < TN / 4; j++)
            *(float4*)(out + oaddr + 4 * j) = *(float4*)(v + 4 * j);
    }
}

// ---------------- enc1: 4x4 s2, 3->64, pad 1, relu ----------------
__global__ void enc1_kernel(const float* __restrict__ x, const float* __restrict__ w,
                            const float* __restrict__ b, float* __restrict__ out) {
    int t = blockIdx.x * 256 + threadIdx.x;
    int oc = t & 63;
    int r = t >> 6;
    int ow = r & 127;
    int oh = (r >> 7) & 127;
    int n  = r >> 14;
    float acc = b[oc];
#pragma unroll
    for (int kh = 0; kh < 4; kh++) {
        int ih = 2 * oh - 1 + kh;
        if ((unsigned)ih >= 256u) continue;
#pragma unroll
        for (int kw = 0; kw < 4; kw++) {
            int iw = 2 * ow - 1 + kw;
            if ((unsigned)iw >= 256u) continue;
            const float* xp = x + ((n * 256 + ih) * 256 + iw) * 3;
            const float* wp = w + (kh * 4 + kw) * 3 * 64 + oc;
            acc = fmaf(xp[0], wp[0],   acc);
            acc = fmaf(xp[1], wp[64],  acc);
            acc = fmaf(xp[2], wp[128], acc);
        }
    }
    out[t] = fmaxf(acc, 0.f);
}

// ---------------- 1x1 conv (relu on input) + residual add, 32->128 ----------------
// Weights ORIGINAL layout [ic][oc] (oc contiguous -> coalesced).
template<bool RELU_OUT>
__global__ void conv1x1_res(const float* __restrict__ tin, const float* __restrict__ res,
                            const float* __restrict__ w, float* __restrict__ out) {
    int t = blockIdx.x * 256 + threadIdx.x;
    int oc = t & 127;
    long p0 = (long)(t >> 7) * 4;
    float wv[32];
#pragma unroll
    for (int ic = 0; ic < 32; ic++) wv[ic] = w[ic * 128 + oc];
    float accp[4] = {0.f, 0.f, 0.f, 0.f};
#pragma unroll
    for (int ic4 = 0; ic4 < 8; ic4++) {
#pragma unroll
        for (int p = 0; p < 4; p++) {
            float4 tv = *(const float4*)(tin + (p0 + p) * 32 + 4 * ic4);
            tv = relu4(tv);
            accp[p] = fmaf(tv.x, wv[4 * ic4],     accp[p]);
            accp[p] = fmaf(tv.y, wv[4 * ic4 + 1], accp[p]);
            accp[p] = fmaf(tv.z, wv[4 * ic4 + 2], accp[p]);
            accp[p] = fmaf(tv.w, wv[4 * ic4 + 3], accp[p]);
        }
    }
    long o = p0 * 128 + oc;
#pragma unroll
    for (int p = 0; p < 4; p++) {
        float v = res[o + p * 128] + accp[p];
        if (RELU_OUT) v = fmaxf(v, 0.f);
        out[o + p * 128] = v;
    }
}

// ---------------- VQ: 16 pixels per block, coalesced codebook ----------------
__global__ void __launch_bounds__(128) vq16(const float* __restrict__ f,
                                            const float* __restrict__ embT,
                                            const float* __restrict__ emb,
                                            const float* __restrict__ norme,
                                            float* __restrict__ q) {
    __shared__ float4 xs4[16 * 32];
    __shared__ float rdist[16 * 128];
    __shared__ int   ridx[16 * 128];
    __shared__ int   best[16];
    int tid = threadIdx.x;
    long pixel0 = (long)blockIdx.x * 16;
    const float4* fin = (const float4*)(f + pixel0 * 128);
#pragma unroll
    for (int i = 0; i < 4; i++) xs4[tid + 128 * i] = fin[tid + 128 * i];
    __syncthreads();

    float acc[4][16];
#pragma unroll
    for (int j = 0; j < 4; j++)
#pragma unroll
        for (int p = 0; p < 16; p++) acc[j][p] = 0.f;

    const float4* eT = (const float4*)embT;
    for (int d4 = 0; d4 < 32; d4++) {
        float4 ev[4];
#pragma unroll
        for (int j = 0; j < 4; j++) ev[j] = eT[d4 * 512 + 128 * j + tid];
#pragma unroll
        for (int p = 0; p < 16; p++) {
            float4 xv = xs4[p * 32 + d4];
#pragma unroll
            for (int j = 0; j < 4; j++) {
                acc[j][p] = fmaf(xv.x, ev[j].x, acc[j][p]);
                acc[j][p] = fmaf(xv.y, ev[j].y, acc[j][p]);
                acc[j][p] = fmaf(xv.z, ev[j].z, acc[j][p]);
                acc[j][p] = fmaf(xv.w, ev[j].w, acc[j][p]);
            }
        }
    }
    float nd[4];
#pragma unroll
    for (int j = 0; j < 4; j++) nd[j] = norme[tid + 128 * j];
#pragma unroll
    for (int p = 0; p < 16; p++) {
        float bd = 1e30f; int bi = 0;
#pragma unroll
        for (int j = 0; j < 4; j++) {
            float d = nd[j] - 2.f * acc[j][p];
            if (d < bd) { bd = d; bi = tid + 128 * j; }
        }
        rdist[p * 128 + tid] = bd;
        ridx[p * 128 + tid]  = bi;
    }
    __syncthreads();
    if (tid < 16) {
        float bd = 1e30f; int bi = 1 << 30;
        for (int u = 0; u < 128; u++) {
            float d = rdist[tid * 128 + u];
            int   i = ridx[tid * 128 + u];
            if (d < bd || (d == bd && i < bi)) { bd = d; bi = i; }
        }
        best[tid] = bi;
    }
    __syncthreads();
#pragma unroll
    for (int p = 0; p < 16; p++)
        q[(pixel0 + p) * 128 + tid] = emb[best[p] * 128 + tid];
}

// ---------------- dt2: conv_transpose 4x4 s2, 64->3; wt [k][oc][ic] ----------------
__global__ void dt2_kernel(const float* __restrict__ in, const float* __restrict__ wt,
                           const float* __restrict__ b, float* __restrict__ out) {
    int t = blockIdx.x * 256 + threadIdx.x;
    int ow = t & 255;
    int oh = (t >> 8) & 255;
    int n  = t >> 16;
    float a0 = b[0], a1 = b[1], a2 = b[2];
#pragma unroll
    for (int dh = 0; dh < 2; dh++) {
        int kh = (oh & 1) + 2 * dh;
        int ih2 = oh + kh - 2;
        if (ih2 < 0 || ih2 >= 256) continue;
        int ih = ih2 >> 1;
#pragma unroll
        for (int dw = 0; dw < 2; dw++) {
            int kw = (ow & 1) + 2 * dw;
            int iw2 = ow + kw - 2;
            if (iw2 < 0 || iw2 >= 256) continue;
            int iw = iw2 >> 1;
            const float4* xp = (const float4*)(in + ((n * 128 + ih) * 128 + iw) * 64);
            const float* wb = wt + (kh * 4 + kw) * 3 * 64;
            const float4* w0 = (const float4*)(wb);
            const float4* w1 = (const float4*)(wb + 64);
            const float4* w2 = (const float4*)(wb + 128);
#pragma unroll 4
            for (int ic4 = 0; ic4 < 16; ic4++) {
                float4 x4 = xp[ic4];
                a0 += dot4(x4, w0[ic4]);
                a1 += dot4(x4, w1[ic4]);
                a2 += dot4(x4, w2[ic4]);
            }
        }
    }
    float* op = out + (long)((n * 256 + oh) * 256 + ow) * 3;
    op[0] = a0; op[1] = a1; op[2] = a2;
}

extern "C" void kernel_launch(void* const* d_in, const int* in_sizes, int n_in,
                              void* d_out, int out_size) {
    const float* x       = (const float*)d_in[0];
    const float* emb     = (const float*)d_in[1];
    const float* enc_w1  = (const float*)d_in[2];
    const float* enc_b1  = (const float*)d_in[3];
    const float* enc_w2  = (const float*)d_in[4];
    const float* enc_b2  = (const float*)d_in[5];
    const float* enc_w3  = (const float*)d_in[6];
    const float* enc_b3  = (const float*)d_in[7];
    const float* erb1_w1 = (const float*)d_in[8];
    const float* erb1_w2 = (const float*)d_in[9];
    const float* erb2_w1 = (const float*)d_in[10];
    const float* erb2_w2 = (const float*)d_in[11];
    const float* dec_w   = (const float*)d_in[12];
    const float* dec_b   = (const float*)d_in[13];
    const float* drb1_w1 = (const float*)d_in[14];
    const float* drb1_w2 = (const float*)d_in[15];
    const float* drb2_w1 = (const float*)d_in[16];
    const float* drb2_w2 = (const float*)d_in[17];
    const float* dt1_w   = (const float*)d_in[18];
    const float* dt1_b   = (const float*)d_in[19];
    const float* dt2_w   = (const float*)d_in[20];
    const float* dt2_b   = (const float*)d_in[21];

    float *pA, *pB1, *pB2, *pT, *pN, *pE, *pWdt2;
    cudaGetSymbolAddress((void**)&pA,    g_A);
    cudaGetSymbolAddress((void**)&pB1,   g_B1);
    cudaGetSymbolAddress((void**)&pB2,   g_B2);
    cudaGetSymbolAddress((void**)&pT,    g_T);
    cudaGetSymbolAddress((void**)&pN,    g_norme);
    cudaGetSymbolAddress((void**)&pE,    g_embT);
    cudaGetSymbolAddress((void**)&pWdt2, g_wdt2);

    float* yout = (float*)d_out;
    float* fout = yout + Y_SZ;
    float* qout = fout + F_SZ;

    // prep
    transpose_w<<<12, 256>>>(dt2_w, pWdt2, 16, 64, 3);
    norme_kernel<<<2, 256>>>(emb, pN);
    embT_kernel<<<64, 256>>>(emb, pE);

    // Encoder
    enc1_kernel<<<65536, 256>>>(x, enc_w1, enc_b1, pA);
    conv_gemm<0, 4, 4, 2, 1, 128, 64, 128, 128, 8, 8, false, true, true>
        <<<512, 256>>>(pA, enc_w2, enc_b2, pB1);
    conv_gemm<0, 3, 3, 1, 1, 64, 128, 128, 128, 8, 8, false, true, false>
        <<<512, 256>>>(pB1, enc_w3, enc_b3, pB2);
    conv_gemm<0, 3, 3, 1, 1, 64, 128, 32, 256, 8, 4, true, false, false>
        <<<256, 256>>>(pB2, erb1_w1, nullptr, pT);
    conv1x1_res<false><<<8192, 256>>>(pT, pB2, erb1_w2, pB1);
    conv_gemm<0, 3, 3, 1, 1, 64, 128, 32, 256, 8, 4, true, false, false>
        <<<256, 256>>>(pB1, erb2_w1, nullptr, pT);
    conv1x1_res<true><<<8192, 256>>>(pT, pB1, erb2_w2, fout);   // f -> d_out

    // VQ
    vq16<<<4096, 128>>>(fout, pE, emb, pN, qout);               // q -> d_out

    // Decoder
    conv_gemm<0, 3, 3, 1, 1, 64, 128, 128, 128, 8, 8, false, true, false>
        <<<512, 256>>>(qout, dec_w, dec_b, pB1);
    conv_gemm<0, 3, 3, 1, 1, 64, 128, 32, 256, 8, 4, true, false, false>
        <<<256, 256>>>(pB1, drb1_w1, nullptr, pT);
    conv1x1_res<false><<<8192, 256>>>(pT, pB1, drb1_w2, pB2);
    conv_gemm<0, 3, 3, 1, 1, 64, 128, 32, 256, 8, 4, true, false, false>
        <<<256, 256>>>(pB2, drb2_w1, nullptr, pT);
    conv1x1_res<true><<<8192, 256>>>(pT, pB2, drb2_w2, pB1);
    conv_gemm<1, 4, 4, 1, 0, 64, 128, 64, 128, 8, 4, false, true, true>
        <<<dim3(512, 4), 256>>>(pB1, dt1_w, dt1_b, pA);
    dt2_kernel<<<4096, 256>>>(pA, pWdt2, dt2_b, yout);
}

// round 3
// speedup vs baseline: 6.8914x; 1.0280x over previous
#include <cuda_runtime.h>

#define Y_SZ  (16*256*256*3)
#define F_SZ  (16*64*64*128)

__device__ __align__(16) float g_A[16*128*128*64];   // enc1 out / dt1 out
__device__ __align__(16) float g_col[16*128*128*64]; // enc1 im2col (K padded to 64)
__device__ __align__(16) float g_B1[16*64*64*128];
__device__ __align__(16) float g_B2[16*64*64*128];
__device__ __align__(16) float g_T[16*64*64*32];
__device__ __align__(16) float g_norme[512];
__device__ __align__(16) float g_embT[512*128];
__device__ __align__(16) float g_wdt2[16*3*64];
__device__ __align__(16) float g_w1p[64*64];

__device__ __forceinline__ float4 relu4(float4 a) {
    a.x = fmaxf(a.x, 0.f); a.y = fmaxf(a.y, 0.f);
    a.z = fmaxf(a.z, 0.f); a.w = fmaxf(a.w, 0.f);
    return a;
}
__device__ __forceinline__ float dot4(float4 a, float4 b) {
    return fmaf(a.x, b.x, fmaf(a.y, b.y, fmaf(a.z, b.z, a.w * b.w)));
}

// ---- packed fp32x2 helpers (Blackwell FFMA2 path) ----
__device__ __forceinline__ unsigned long long pk2(float x, float y) {
    unsigned long long r;
    asm("mov.b64 %0, {%1, %2};" : "=l"(r)
        : "r"(__float_as_uint(x)), "r"(__float_as_uint(y)));
    return r;
}
__device__ __forceinline__ float2 up2(unsigned long long v) {
    unsigned int lo, hi;
    asm("mov.b64 {%0, %1}, %2;" : "=r"(lo), "=r"(hi) : "l"(v));
    return make_float2(__uint_as_float(lo), __uint_as_float(hi));
}
__device__ __forceinline__ void fma2(unsigned long long& d,
                                     unsigned long long a, unsigned long long b) {
    asm("fma.rn.f32x2 %0, %1, %2, %0;" : "+l"(d) : "l"(a), "l"(b));
}

// [k][ic][oc] -> [k][oc][ic]  (only for dt2 tiny weights)
__global__ void transpose_w(const float* __restrict__ in, float* __restrict__ out,
                            int K, int IC, int OC) {
    int i = blockIdx.x * blockDim.x + threadIdx.x;
    int total = K * IC * OC;
    if (i >= total) return;
    int oc = i % OC;
    int ic = (i / OC) % IC;
    int k  = i / (OC * IC);
    out[(k * OC + oc) * IC + ic] = in[i];
}

__global__ void norme_kernel(const float* __restrict__ emb, float* __restrict__ norme) {
    int k = blockIdx.x * blockDim.x + threadIdx.x;
    if (k >= 512) return;
    const float4* e = (const float4*)(emb + k * 128);
    float s = 0.f;
#pragma unroll 8
    for (int i = 0; i < 32; i++) {
        float4 v = e[i];
        s = fmaf(v.x, v.x, s); s = fmaf(v.y, v.y, s);
        s = fmaf(v.z, v.z, s); s = fmaf(v.w, v.w, s);
    }
    norme[k] = s;
}

// emb [c][d] -> embT float4 layout [d4][c]
__global__ void embT_kernel(const float* __restrict__ emb, float* __restrict__ embT) {
    int i = blockIdx.x * 256 + threadIdx.x;
    if (i >= 512 * 32) return;
    int c = i & 511, d4 = i >> 9;
    float4 v = *(const float4*)(emb + c * 128 + 4 * d4);
    *(float4*)(embT + (d4 * 512 + c) * 4) = v;
}

// enc1 weights [48][64] -> padded [64][64] (zeros beyond row 47)
__global__ void pad_w1(const float* __restrict__ w, float* __restrict__ out) {
    int t = blockIdx.x * 256 + threadIdx.x;
    if (t >= 64 * 64) return;
    int r = t >> 6;
    out[t] = (r < 48) ? w[t] : 0.f;
}

// enc1 im2col: col[p][64], kidx = kh*12 + kw*3 + ic (rows 48..63 zero)
__global__ void im2col_enc1(const float* __restrict__ x, float* __restrict__ col) {
    int t = blockIdx.x * 256 + threadIdx.x;   // over 262144*64
    int kidx = t & 63;
    int p = t >> 6;
    int ow = p & 127, oh = (p >> 7) & 127, n = p >> 14;
    float v = 0.f;
    if (kidx < 48) {
        int ic = kidx % 3;
        int kw = (kidx / 3) & 3;
        int kh = kidx / 12;
        int ih = 2 * oh - 1 + kh, iw = 2 * ow - 1 + kw;
        if ((unsigned)ih < 256u && (unsigned)iw < 256u)
            v = x[((n * 256 + ih) * 256 + iw) * 3 + ic];
    }
    col[t] = v;
}

// ================= tiled implicit-GEMM conv (fp32x2 core) =================
// MODE 0: standard conv (KHxKW, stride, pad) square IH input grid, 64x64 out grid.
// MODE 1: dt1 deconv per parity class (blockIdx.y), output scattered to 128x128.
// MODE 2: flat GEMM: in[p][IC], out[p][OC].
// Weights ORIGINAL layout [tap][ic][oc].
template<int MODE, int KH, int KW, int STRIDE, int PAD, int IH,
         int IC, int OC, int BM, int TM, int TN,
         bool RELU_IN, bool HAS_BIAS, bool RELU_OUT>
__global__ void __launch_bounds__(256, 2) conv_gemm(
    const float* __restrict__ in, const float* __restrict__ w,
    const float* __restrict__ bias, float* __restrict__ out)
{
    constexpr int BK = 32;
    constexpr int BN = OC;
    constexpr int TX = BN / TN;
    constexpr int ASTR = BM + 2;          // even: 8B-aligned pair reads
    constexpr int NTAPS = (MODE == 0) ? KH * KW : ((MODE == 1) ? 4 : 1);
    constexpr int SE = (MODE == 0) ? STRIDE : 1;

    __shared__ __align__(16) float As[BK * ASTR];
    __shared__ __align__(16) float Bs[BK * BN];

    int tid = threadIdx.x;
    int m0 = blockIdx.x * BM;
    int po = 0, pw = 0;
    if (MODE == 1) { po = blockIdx.y >> 1; pw = blockIdx.y & 1; }

    int tx = tid % TX, ty = tid / TX;
    int c4 = tid & 7;
    int mp = tid >> 3;

    unsigned long long acc2[TM / 2][TN];
#pragma unroll
    for (int i = 0; i < TM / 2; i++)
#pragma unroll
        for (int j = 0; j < TN; j++) acc2[i][j] = 0ull;

    for (int tap = 0; tap < NTAPS; tap++) {
        int hoff = 0, woff = 0, wtap = 0;
        if (MODE == 0) {
            int kh = tap / KW, kw = tap % KW;
            hoff = kh - PAD; woff = kw - PAD; wtap = tap;
        } else if (MODE == 1) {
            int dh = tap >> 1, dw = tap & 1;
            hoff = po + dh - 1; woff = pw + dw - 1;
            wtap = (po + 2 * dh) * 4 + (pw + 2 * dw);
        }
        for (int kc = 0; kc < IC / BK; kc++) {
            __syncthreads();
            // ---- A tile (BM pixels x BK channels) -> As[k][m]
#pragma unroll
            for (int pass = 0; pass < BM / 32; pass++) {
                int m = mp + pass * 32;
                int p = m0 + m;
                float4 v;
                if (MODE == 2) {
                    v = *(const float4*)(in + (long)p * IC + kc * BK + 4 * c4);
                } else {
                    int n_img = p >> 12;
                    int oh = (p >> 6) & 63;
                    int ow = p & 63;
                    int ih = oh * SE + hoff;
                    int iw = ow * SE + woff;
                    v = make_float4(0.f, 0.f, 0.f, 0.f);
                    if ((unsigned)ih < (unsigned)IH && (unsigned)iw < (unsigned)IH) {
                        v = *(const float4*)(in + ((n_img * IH + ih) * IH + iw) * IC
                                                + kc * BK + 4 * c4);
                        if (RELU_IN) v = relu4(v);
                    }
                }
                int kk = 4 * c4;
                As[(kk + 0) * ASTR + m] = v.x;
                As[(kk + 1) * ASTR + m] = v.y;
                As[(kk + 2) * ASTR + m] = v.z;
                As[(kk + 3) * ASTR + m] = v.w;
            }
            // ---- B tile (BK x BN), oc contiguous -> coalesced
            {
                const float* wb = w + (wtap * IC + kc * BK) * OC;
#pragma unroll
                for (int i = 0; i < (BK * BN / 4) / 256; i++) {
                    int idx = tid + i * 256;
                    int kr = idx / (BN / 4);
                    int n4 = idx % (BN / 4);
                    *(float4*)(Bs + kr * BN + 4 * n4) =
                        *(const float4*)(wb + kr * OC + 4 * n4);
                }
            }
            __syncthreads();
            // ---- fp32x2 inner product
#pragma unroll 8
            for (int k = 0; k < BK; k++) {
                unsigned long long a2[TM / 2], b2[TN];
                const double* ap = (const double*)(As + k * ASTR + ty * TM);
#pragma unroll
                for (int i = 0; i < TM / 2; i++)
                    a2[i] = __double_as_longlong(ap[i]);
                float b[TN];
#pragma unroll
                for (int j = 0; j < TN / 4; j++)
                    *(float4*)(b + 4 * j) = *(const float4*)(Bs + k * BN + tx * TN + 4 * j);
#pragma unroll
                for (int j = 0; j < TN; j++) b2[j] = pk2(b[j], b[j]);
#pragma unroll
                for (int i = 0; i < TM / 2; i++)
#pragma unroll
                    for (int j = 0; j < TN; j++)
                        fma2(acc2[i][j], a2[i], b2[j]);
            }
        }
    }
    // ---- epilogue
    float bv[TN];
#pragma unroll
    for (int j = 0; j < TN; j++) bv[j] = HAS_BIAS ? bias[tx * TN + j] : 0.f;
    int base_m = m0 + ty * TM;
#pragma unroll
    for (int i2 = 0; i2 < TM / 2; i2++) {
        float2 tv[TN];
#pragma unroll
        for (int j = 0; j < TN; j++) tv[j] = up2(acc2[i2][j]);
#pragma unroll
        for (int h = 0; h < 2; h++) {
            int p = base_m + 2 * i2 + h;
            float v[TN];
#pragma unroll
            for (int j = 0; j < TN; j++) {
                float t = (h ? tv[j].y : tv[j].x) + bv[j];
                v[j] = RELU_OUT ? fmaxf(t, 0.f) : t;
            }
            long oaddr;
            if (MODE == 1) {
                int n_img = p >> 12, a2i = (p >> 6) & 63, b2i = p & 63;
                oaddr = (((long)n_img * 128 + 2 * a2i + po) * 128 + 2 * b2i + pw) * OC
                        + tx * TN;
            } else {
                oaddr = (long)p * OC + tx * TN;
            }
#pragma unroll
            for (int j = 0; j < TN / 4; j++)
                *(float4*)(out + oaddr + 4 * j) = *(float4*)(v + 4 * j);
        }
    }
}

// ---------------- 1x1 conv (relu on input) + residual add, 32->128 ----------------
template<bool RELU_OUT>
__global__ void conv1x1_res(const float* __restrict__ tin, const float* __restrict__ res,
                            const float* __restrict__ w, float* __restrict__ out) {
    int t = blockIdx.x * 256 + threadIdx.x;
    int oc = t & 127;
    long p0 = (long)(t >> 7) * 4;
    float wv[32];
#pragma unroll
    for (int ic = 0; ic < 32; ic++) wv[ic] = w[ic * 128 + oc];
    float accp[4] = {0.f, 0.f, 0.f, 0.f};
#pragma unroll
    for (int ic4 = 0; ic4 < 8; ic4++) {
#pragma unroll
        for (int p = 0; p < 4; p++) {
            float4 tv = *(const float4*)(tin + (p0 + p) * 32 + 4 * ic4);
            tv = relu4(tv);
            accp[p] = fmaf(tv.x, wv[4 * ic4],     accp[p]);
            accp[p] = fmaf(tv.y, wv[4 * ic4 + 1], accp[p]);
            accp[p] = fmaf(tv.z, wv[4 * ic4 + 2], accp[p]);
            accp[p] = fmaf(tv.w, wv[4 * ic4 + 3], accp[p]);
        }
    }
    long o = p0 * 128 + oc;
#pragma unroll
    for (int p = 0; p < 4; p++) {
        float v = res[o + p * 128] + accp[p];
        if (RELU_OUT) v = fmaxf(v, 0.f);
        out[o + p * 128] = v;
    }
}

// ---------------- VQ: 16 pixels/block, fp32x2 pixel-pair accumulators ----------------
__global__ void __launch_bounds__(128) vq16(const float* __restrict__ f,
                                            const float* __restrict__ embT,
                                            const float* __restrict__ emb,
                                            const float* __restrict__ norme,
                                            float* __restrict__ q) {
    __shared__ float4 xs4[16 * 32];
    __shared__ float rdist[16 * 128];
    __shared__ int   ridx[16 * 128];
    __shared__ int   best[16];
    int tid = threadIdx.x;
    long pixel0 = (long)blockIdx.x * 16;
    const float4* fin = (const float4*)(f + pixel0 * 128);
#pragma unroll
    for (int i = 0; i < 4; i++) xs4[tid + 128 * i] = fin[tid + 128 * i];
    __syncthreads();

    unsigned long long acc2[4][8];
#pragma unroll
    for (int j = 0; j < 4; j++)
#pragma unroll
        for (int p2 = 0; p2 < 8; p2++) acc2[j][p2] = 0ull;

    const float4* eT = (const float4*)embT;
    for (int d4 = 0; d4 < 32; d4++) {
        float4 ev[4];
#pragma unroll
        for (int j = 0; j < 4; j++) ev[j] = eT[d4 * 512 + 128 * j + tid];
        unsigned long long e2[4][4];
#pragma unroll
        for (int j = 0; j < 4; j++) {
            e2[j][0] = pk2(ev[j].x, ev[j].x);
            e2[j][1] = pk2(ev[j].y, ev[j].y);
            e2[j][2] = pk2(ev[j].z, ev[j].z);
            e2[j][3] = pk2(ev[j].w, ev[j].w);
        }
#pragma unroll
        for (int p2 = 0; p2 < 8; p2++) {
            float4 xa = xs4[(2 * p2) * 32 + d4];
            float4 xb = xs4[(2 * p2 + 1) * 32 + d4];
            unsigned long long xp0 = pk2(xa.x, xb.x);
            unsigned long long xp1 = pk2(xa.y, xb.y);
            unsigned long long xp2 = pk2(xa.z, xb.z);
            unsigned long long xp3 = pk2(xa.w, xb.w);
#pragma unroll
            for (int j = 0; j < 4; j++) {
                fma2(acc2[j][p2], xp0, e2[j][0]);
                fma2(acc2[j][p2], xp1, e2[j][1]);
                fma2(acc2[j][p2], xp2, e2[j][2]);
                fma2(acc2[j][p2], xp3, e2[j][3]);
            }
        }
    }
    float accs[4][16];
#pragma unroll
    for (int j = 0; j < 4; j++)
#pragma unroll
        for (int p2 = 0; p2 < 8; p2++) {
            float2 u = up2(acc2[j][p2]);
            accs[j][2 * p2] = u.x;
            accs[j][2 * p2 + 1] = u.y;
        }
    float nd[4];
#pragma unroll
    for (int j = 0; j < 4; j++) nd[j] = norme[tid + 128 * j];
#pragma unroll
    for (int p = 0; p < 16; p++) {
        float bd = 1e30f; int bi = 0;
#pragma unroll
        for (int j = 0; j < 4; j++) {
            float d = nd[j] - 2.f * accs[j][p];
            if (d < bd) { bd = d; bi = tid + 128 * j; }
        }
        rdist[p * 128 + tid] = bd;
        ridx[p * 128 + tid]  = bi;
    }
    __syncthreads();
    if (tid < 16) {
        float bd = 1e30f; int bi = 1 << 30;
        for (int u = 0; u < 128; u++) {
            float d = rdist[tid * 128 + u];
            int   i = ridx[tid * 128 + u];
            if (d < bd || (d == bd && i < bi)) { bd = d; bi = i; }
        }
        best[tid] = bi;
    }
    __syncthreads();
#pragma unroll
    for (int p = 0; p < 16; p++)
        q[(pixel0 + p) * 128 + tid] = emb[best[p] * 128 + tid];
}

// ---------------- dt2: conv_transpose 4x4 s2, 64->3; wt [k][oc][ic] ----------------
__global__ void dt2_kernel(const float* __restrict__ in, const float* __restrict__ wt,
                           const float* __restrict__ b, float* __restrict__ out) {
    int t = blockIdx.x * 256 + threadIdx.x;
    int ow = t & 255;
    int oh = (t >> 8) & 255;
    int n  = t >> 16;
    float a0 = b[0], a1 = b[1], a2 = b[2];
#pragma unroll
    for (int dh = 0; dh < 2; dh++) {
        int kh = (oh & 1) + 2 * dh;
        int ih2 = oh + kh - 2;
        if (ih2 < 0 || ih2 >= 256) continue;
        int ih = ih2 >> 1;
#pragma unroll
        for (int dw = 0; dw < 2; dw++) {
            int kw = (ow & 1) + 2 * dw;
            int iw2 = ow + kw - 2;
            if (iw2 < 0 || iw2 >= 256) continue;
            int iw = iw2 >> 1;
            const float4* xp = (const float4*)(in + ((n * 128 + ih) * 128 + iw) * 64);
            const float* wb = wt + (kh * 4 + kw) * 3 * 64;
            const float4* w0 = (const float4*)(wb);
            const float4* w1 = (const float4*)(wb + 64);
            const float4* w2 = (const float4*)(wb + 128);
#pragma unroll 4
            for (int ic4 = 0; ic4 < 16; ic4++) {
                float4 x4 = xp[ic4];
                a0 += dot4(x4, w0[ic4]);
                a1 += dot4(x4, w1[ic4]);
                a2 += dot4(x4, w2[ic4]);
            }
        }
    }
    float* op = out + (long)((n * 256 + oh) * 256 + ow) * 3;
    op[0] = a0; op[1] = a1; op[2] = a2;
}

extern "C" void kernel_launch(void* const* d_in, const int* in_sizes, int n_in,
                              void* d_out, int out_size) {
    const float* x       = (const float*)d_in[0];
    const float* emb     = (const float*)d_in[1];
    const float* enc_w1  = (const float*)d_in[2];
    const float* enc_b1  = (const float*)d_in[3];
    const float* enc_w2  = (const float*)d_in[4];
    const float* enc_b2  = (const float*)d_in[5];
    const float* enc_w3  = (const float*)d_in[6];
    const float* enc_b3  = (const float*)d_in[7];
    const float* erb1_w1 = (const float*)d_in[8];
    const float* erb1_w2 = (const float*)d_in[9];
    const float* erb2_w1 = (const float*)d_in[10];
    const float* erb2_w2 = (const float*)d_in[11];
    const float* dec_w   = (const float*)d_in[12];
    const float* dec_b   = (const float*)d_in[13];
    const float* drb1_w1 = (const float*)d_in[14];
    const float* drb1_w2 = (const float*)d_in[15];
    const float* drb2_w1 = (const float*)d_in[16];
    const float* drb2_w2 = (const float*)d_in[17];
    const float* dt1_w   = (const float*)d_in[18];
    const float* dt1_b   = (const float*)d_in[19];
    const float* dt2_w   = (const float*)d_in[20];
    const float* dt2_b   = (const float*)d_in[21];

    float *pA, *pCol, *pB1, *pB2, *pT, *pN, *pE, *pWdt2, *pW1p;
    cudaGetSymbolAddress((void**)&pA,    g_A);
    cudaGetSymbolAddress((void**)&pCol,  g_col);
    cudaGetSymbolAddress((void**)&pB1,   g_B1);
    cudaGetSymbolAddress((void**)&pB2,   g_B2);
    cudaGetSymbolAddress((void**)&pT,    g_T);
    cudaGetSymbolAddress((void**)&pN,    g_norme);
    cudaGetSymbolAddress((void**)&pE,    g_embT);
    cudaGetSymbolAddress((void**)&pWdt2, g_wdt2);
    cudaGetSymbolAddress((void**)&pW1p,  g_w1p);

    float* yout = (float*)d_out;
    float* fout = yout + Y_SZ;
    float* qout = fout + F_SZ;

    // prep
    transpose_w<<<12, 256>>>(dt2_w, pWdt2, 16, 64, 3);
    norme_kernel<<<2, 256>>>(emb, pN);
    embT_kernel<<<64, 256>>>(emb, pE);
    pad_w1<<<16, 256>>>(enc_w1, pW1p);

    // Encoder
    im2col_enc1<<<65536, 256>>>(x, pCol);
    conv_gemm<2, 1, 1, 1, 0, 0, 64, 64, 128, 8, 4, false, true, true>
        <<<2048, 256>>>(pCol, pW1p, enc_b1, pA);
    conv_gemm<0, 4, 4, 2, 1, 128, 64, 128, 128, 8, 8, false, true, true>
        <<<512, 256>>>(pA, enc_w2, enc_b2, pB1);
    conv_gemm<0, 3, 3, 1, 1, 64, 128, 128, 128, 8, 8, false, true, false>
        <<<512, 256>>>(pB1, enc_w3, enc_b3, pB2);
    conv_gemm<0, 3, 3, 1, 1, 64, 128, 32, 256, 8, 4, true, false, false>
        <<<256, 256>>>(pB2, erb1_w1, nullptr, pT);
    conv1x1_res<false><<<8192, 256>>>(pT, pB2, erb1_w2, pB1);
    conv_gemm<0, 3, 3, 1, 1, 64, 128, 32, 256, 8, 4, true, false, false>
        <<<256, 256>>>(pB1, erb2_w1, nullptr, pT);
    conv1x1_res<true><<<8192, 256>>>(pT, pB1, erb2_w2, fout);   // f -> d_out

    // VQ
    vq16<<<4096, 128>>>(fout, pE, emb, pN, qout);               // q -> d_out

    // Decoder
    conv_gemm<0, 3, 3, 1, 1, 64, 128, 128, 128, 8, 8, false, true, false>
        <<<512, 256>>>(qout, dec_w, dec_b, pB1);
    conv_gemm<0, 3, 3, 1, 1, 64, 128, 32, 256, 8, 4, true, false, false>
        <<<256, 256>>>(pB1, drb1_w1, nullptr, pT);
    conv1x1_res<false><<<8192, 256>>>(pT, pB1, drb1_w2, pB2);
    conv_gemm<0, 3, 3, 1, 1, 64, 128, 32, 256, 8, 4, true, false, false>
        <<<256, 256>>>(pB2, drb2_w1, nullptr, pT);
    conv1x1_res<true><<<8192, 256>>>(pT, pB2, drb2_w2, pB1);
    conv_gemm<1, 4, 4, 1, 0, 64, 128, 64, 128, 8, 4, false, true, true>
        <<<dim3(512, 4), 256>>>(pB1, dt1_w, dt1_b, pA);
    dt2_kernel<<<4096, 256>>>(pA, pWdt2, dt2_b, yout);
}